// round 6
// baseline (speedup 1.0000x reference)
#include <cuda_runtime.h>
#include <math.h>

#define NN      512
#define D       32
#define M       32
#define HM      64
#define HRO     64
#define NSTEPS  5

#define TJ 32      // j per block
#define LI 4       // i per thread (sequential)
#define GI 8       // i-groups (warps) per block
#define TI (LI*GI) // 32 i per block

// Scratch (device globals: no allocation allowed)
__device__ float g_h[2][NN*D];
__device__ float g_A[NN*HM];
__device__ float g_B[NN*HM];
__device__ float g_msgsum[NN*M];

__device__ __forceinline__ float sigmoidf(float x) { return 1.f / (1.f + expf(-x)); }

// ---------------------------------------------------------------------------
// Zero the initial hidden state (must run every replay: graph-deterministic)
// ---------------------------------------------------------------------------
__global__ void zero_h0_kernel() {
    int idx = blockIdx.x * blockDim.x + threadIdx.x;
    if (idx < NN * D) g_h[0][idx] = 0.f;
}

// ---------------------------------------------------------------------------
// Prep: A[i,k] = h[i]·Wi[k] + b[i]*wbi[k] + b1[k] ;  B[i,k] = h[i]·Wj[k] + b[i]*wbj[k]
// Also zeroes msgsum. mp_W1 is (64, 67): [Wi(32) | Wj(32) | wJ | wbi | wbj]
// ---------------------------------------------------------------------------
__global__ void prep_kernel(const float* __restrict__ b,
                            const float* __restrict__ W1,
                            const float* __restrict__ b1,
                            int cur) {
    __shared__ float hs[D];
    int i = blockIdx.x;
    int k = threadIdx.x;          // 0..63
    if (k < D) hs[k] = g_h[cur][i*D + k];
    __syncthreads();
    float bi = b[i];
    const float* row = W1 + k * 67;
    float a  = b1[k] + bi * row[65];
    float bb = bi * row[66];
    #pragma unroll
    for (int d0 = 0; d0 < D; d0++) {
        float hv = hs[d0];
        a  = fmaf(hv, row[d0],     a);
        bb = fmaf(hv, row[D + d0], bb);
    }
    g_A[i*HM + k] = a;
    g_B[i*HM + k] = bb;
    if (k < M) g_msgsum[i*M + k] = 0.f;
}

// ---------------------------------------------------------------------------
// Edge MLP: for each (i,j):
//   m1  = relu(A[i] + B[j] + J[i,j]*wJ)            (64)
//   m2  = relu(m1 @ W2^T + b2)                     (64)
//   msg = relu(m2 @ W3^T + b3)                     (32)
//   msgsum[j] += msg     (sum over i)
// Block: TJ=32 j, TI=32 i. warp = one i-group; lane = j. Thread walks LI=4 i's.
// ---------------------------------------------------------------------------
__global__ __launch_bounds__(256, 1)
void edge_kernel(const float* __restrict__ J,
                 const float* __restrict__ W1,
                 const float* __restrict__ W2,
                 const float* __restrict__ b2,
                 const float* __restrict__ W3,
                 const float* __restrict__ b3) {
    __shared__ float As[TI][HM];        // broadcast reads (per-warp same i)
    __shared__ float Bs[TJ][HM + 4];    // pad 68 -> conflict-free LDS.128 across lanes
    __shared__ float W2s[HM][HM];       // broadcast reads
    __shared__ float W3Ts[HM][M];       // transposed, broadcast reads
    __shared__ float wJs[HM];
    __shared__ float b2s[HM];
    __shared__ float b3s[M];

    const int tid = threadIdx.x;
    const int j0 = blockIdx.x * TJ;
    const int i0 = blockIdx.y * TI;

    for (int idx = tid; idx < HM*HM; idx += 256) ((float*)W2s)[idx] = W2[idx];
    for (int idx = tid; idx < M*HM;  idx += 256) {
        int km = idx >> 6, k2 = idx & 63;   // W3 is (M, HM) row-major
        W3Ts[k2][km] = W3[idx];
    }
    for (int idx = tid; idx < TI*HM; idx += 256) ((float*)As)[idx] = g_A[i0*HM + idx];
    for (int idx = tid; idx < TJ*HM; idx += 256) {
        int r = idx >> 6, c = idx & 63;
        Bs[r][c] = g_B[j0*HM + idx];
    }
    if (tid < HM) { wJs[tid] = W1[tid*67 + 64]; b2s[tid] = b2[tid]; }
    if (tid < M)  b3s[tid] = b3[tid];

    const int g  = tid >> 5;   // i-group (warp)
    const int jj = tid & 31;   // lane -> j
    const int j  = j0 + jj;

    // Prefetch all LI J values before the compute loop: MLP=4 batched LDGs,
    // DRAM/L2 latency hidden under the smem-fill barrier + first MLP body.
    float Jw_pre[LI];
    #pragma unroll
    for (int il = 0; il < LI; il++)
        Jw_pre[il] = __ldg(&J[(i0 + g*LI + il)*NN + j]);   // coalesced across lanes

    __syncthreads();

    float msgacc[M];
    #pragma unroll
    for (int k = 0; k < M; k++) msgacc[k] = 0.f;

    for (int il = 0; il < LI; il++) {
        const int i_local = g * LI + il;
        const float Jw = Jw_pre[il];

        // m1 = relu(A + B + Jw*wJ)
        float m1v[HM];
        #pragma unroll
        for (int k4 = 0; k4 < HM/4; k4++) {
            float4 a  = *(const float4*)&As[i_local][k4*4];
            float4 bb = *(const float4*)&Bs[jj][k4*4];
            float4 w  = *(const float4*)&wJs[k4*4];
            m1v[k4*4+0] = fmaxf(fmaf(Jw, w.x, a.x + bb.x), 0.f);
            m1v[k4*4+1] = fmaxf(fmaf(Jw, w.y, a.y + bb.y), 0.f);
            m1v[k4*4+2] = fmaxf(fmaf(Jw, w.z, a.z + bb.z), 0.f);
            m1v[k4*4+3] = fmaxf(fmaf(Jw, w.w, a.w + bb.w), 0.f);
        }

        float mp[M];
        #pragma unroll
        for (int k = 0; k < M; k++) mp[k] = 0.f;

        // fused GEMM1 (m1 @ W2^T) + GEMM2 (relu(m2) @ W3^T)
        #pragma unroll 8
        for (int k2 = 0; k2 < HM; k2++) {
            float a0 = 0.f, a1 = 0.f, a2 = 0.f, a3 = 0.f;  // 4 chains: hide FFMA latency
            #pragma unroll
            for (int k4 = 0; k4 < HM/4; k4++) {
                float4 w = *(const float4*)&W2s[k2][k4*4];  // broadcast LDS.128
                a0 = fmaf(m1v[k4*4+0], w.x, a0);
                a1 = fmaf(m1v[k4*4+1], w.y, a1);
                a2 = fmaf(m1v[k4*4+2], w.z, a2);
                a3 = fmaf(m1v[k4*4+3], w.w, a3);
            }
            float m2r = fmaxf((a0 + a1) + (a2 + a3) + b2s[k2], 0.f);
            #pragma unroll
            for (int q = 0; q < M/4; q++) {
                float4 w = *(const float4*)&W3Ts[k2][q*4];  // broadcast LDS.128
                mp[q*4+0] = fmaf(m2r, w.x, mp[q*4+0]);
                mp[q*4+1] = fmaf(m2r, w.y, mp[q*4+1]);
                mp[q*4+2] = fmaf(m2r, w.z, mp[q*4+2]);
                mp[q*4+3] = fmaf(m2r, w.w, mp[q*4+3]);
            }
        }
        #pragma unroll
        for (int k = 0; k < M; k++)
            msgacc[k] += fmaxf(mp[k] + b3s[k], 0.f);
    }

    #pragma unroll
    for (int k = 0; k < M; k++)
        atomicAdd(&g_msgsum[j*M + k], msgacc[k]);
}

// ---------------------------------------------------------------------------
// GRU update: one block per node, 96 threads (one per gate row)
// ---------------------------------------------------------------------------
__global__ void gru_kernel(const float* __restrict__ Wih,
                           const float* __restrict__ Whh,
                           const float* __restrict__ bih,
                           const float* __restrict__ bhh,
                           int cur, int nxt) {
    __shared__ float xs[D + M];
    __shared__ float gi[3*D], gh[3*D];
    const int n = blockIdx.x;
    const int t = threadIdx.x;   // 0..95
    if (t < D)          xs[t] = g_h[cur][n*D + t];
    else if (t < D + M) xs[t] = g_msgsum[n*M + (t - D)];
    __syncthreads();

    float a = bih[t];
    const float* wr = Wih + t * (D + M);
    #pragma unroll
    for (int c = 0; c < D + M; c++) a = fmaf(wr[c], xs[c], a);
    gi[t] = a;

    float bq = bhh[t];
    const float* wh = Whh + t * D;
    #pragma unroll
    for (int c = 0; c < D; c++) bq = fmaf(wh[c], xs[c], bq);
    gh[t] = bq;
    __syncthreads();

    if (t < D) {
        float r  = sigmoidf(gi[t]       + gh[t]);
        float z  = sigmoidf(gi[D + t]   + gh[D + t]);
        float ng = tanhf   (gi[2*D + t] + r * gh[2*D + t]);
        g_h[nxt][n*D + t] = (1.f - z) * ng + z * xs[t];
    }
}

// ---------------------------------------------------------------------------
// Readout: y = sigmoid(relu(relu(relu(h@W1^T+b1)@W2^T+b2)@W3^T+b3))
// ---------------------------------------------------------------------------
__global__ void readout_kernel(const float* __restrict__ rW1, const float* __restrict__ rb1,
                               const float* __restrict__ rW2, const float* __restrict__ rb2,
                               const float* __restrict__ rW3, const float* __restrict__ rb3,
                               int cur, float* __restrict__ out) {
    __shared__ float hs[D];
    __shared__ float y1[HRO], y2[HRO];
    const int n = blockIdx.x;
    const int t = threadIdx.x;   // 0..63
    if (t < D) hs[t] = g_h[cur][n*D + t];
    __syncthreads();

    float a = rb1[t];
    #pragma unroll
    for (int c = 0; c < D; c++) a = fmaf(rW1[t*D + c], hs[c], a);
    y1[t] = fmaxf(a, 0.f);
    __syncthreads();

    a = rb2[t];
    #pragma unroll
    for (int c = 0; c < HRO; c++) a = fmaf(rW2[t*HRO + c], y1[c], a);
    y2[t] = fmaxf(a, 0.f);
    __syncthreads();

    if (t < 2) {
        a = rb3[t];
        #pragma unroll
        for (int c = 0; c < HRO; c++) a = fmaf(rW3[t*HRO + c], y2[c], a);
        a = fmaxf(a, 0.f);
        out[n*2 + t] = 1.f / (1.f + expf(-a));
    }
}

// ---------------------------------------------------------------------------
extern "C" void kernel_launch(void* const* d_in, const int* in_sizes, int n_in,
                              void* d_out, int out_size) {
    const float* J   = (const float*)d_in[0];
    const float* b   = (const float*)d_in[1];
    const float* W1  = (const float*)d_in[2];
    const float* b1  = (const float*)d_in[3];
    const float* W2  = (const float*)d_in[4];
    const float* b2  = (const float*)d_in[5];
    const float* W3  = (const float*)d_in[6];
    const float* b3  = (const float*)d_in[7];
    const float* Wih = (const float*)d_in[8];
    const float* Whh = (const float*)d_in[9];
    const float* bih = (const float*)d_in[10];
    const float* bhh = (const float*)d_in[11];
    const float* rW1 = (const float*)d_in[12];
    const float* rb1 = (const float*)d_in[13];
    const float* rW2 = (const float*)d_in[14];
    const float* rb2 = (const float*)d_in[15];
    const float* rW3 = (const float*)d_in[16];
    const float* rb3 = (const float*)d_in[17];
    float* out = (float*)d_out;

    zero_h0_kernel<<<(NN*D + 255)/256, 256>>>();

    int cur = 0;
    for (int s = 0; s < NSTEPS; s++) {
        prep_kernel<<<NN, HM>>>(b, W1, b1, cur);
        edge_kernel<<<dim3(NN/TJ, NN/TI), 256>>>(J, W1, W2, b2, W3, b3);
        gru_kernel<<<NN, 96>>>(Wih, Whh, bih, bhh, cur, 1 - cur);
        cur = 1 - cur;
    }
    readout_kernel<<<NN, HRO>>>(rW1, rb1, rW2, rb2, rW3, rb3, cur, out);
}

// round 7
// speedup vs baseline: 1.1714x; 1.1714x over previous
#include <cuda_runtime.h>
#include <math.h>

#define NN      512
#define D       32
#define M       32
#define HM      64
#define HRO     64
#define NSTEPS  5

#define TJ 32      // j per block
#define LI 4       // i per thread (sequential)
#define GI 8       // i-groups (warps) per block
#define TI (LI*GI) // 32 i per block

// Scratch (device globals: no allocation allowed)
__device__ float g_h[2][NN*D];
__device__ float g_A[NN*HM];
__device__ float g_B[NN*HM];
__device__ float g_msgsum[NN*M];

typedef unsigned long long u64;

__device__ __forceinline__ float sigmoidf(float x) { return 1.f / (1.f + expf(-x)); }

// ---- packed f32x2 helpers (FFMA2: only reachable via PTX fma.rn.f32x2) ----
__device__ __forceinline__ u64 fma2(u64 a, u64 b, u64 c) {
    u64 d; asm("fma.rn.f32x2 %0, %1, %2, %3;" : "=l"(d) : "l"(a), "l"(b), "l"(c)); return d;
}
__device__ __forceinline__ u64 add2(u64 a, u64 b) {
    u64 d; asm("add.rn.f32x2 %0, %1, %2;" : "=l"(d) : "l"(a), "l"(b)); return d;
}
__device__ __forceinline__ u64 pack2(float lo, float hi) {
    u64 d; asm("mov.b64 %0, {%1, %2};" : "=l"(d) : "f"(lo), "f"(hi)); return d;
}
__device__ __forceinline__ void unpack2(u64 v, float& lo, float& hi) {
    asm("mov.b64 {%0, %1}, %2;" : "=f"(lo), "=f"(hi) : "l"(v));
}
__device__ __forceinline__ u64 relu2(u64 v) {   // FMNMX rides the alu pipe, not fma
    float lo, hi; unpack2(v, lo, hi);
    return pack2(fmaxf(lo, 0.f), fmaxf(hi, 0.f));
}

// ---------------------------------------------------------------------------
// Zero the initial hidden state (must run every replay: graph-deterministic)
// ---------------------------------------------------------------------------
__global__ void zero_h0_kernel() {
    int idx = blockIdx.x * blockDim.x + threadIdx.x;
    if (idx < NN * D) g_h[0][idx] = 0.f;
}

// ---------------------------------------------------------------------------
// Prep: A[i,k] = h[i]·Wi[k] + b[i]*wbi[k] + b1[k] ;  B[i,k] = h[i]·Wj[k] + b[i]*wbj[k]
// 8 nodes per block, 512 threads; W1 staged in smem once per block.
// Also zeroes msgsum. mp_W1 is (64, 67): [Wi(32) | Wj(32) | wJ | wbi | wbj]
// ---------------------------------------------------------------------------
#define PREP_NPB 8
__global__ __launch_bounds__(512)
void prep_kernel(const float* __restrict__ b,
                 const float* __restrict__ W1,
                 const float* __restrict__ b1,
                 int cur) {
    __shared__ float W1s[HM * 67];          // 4288 floats
    __shared__ float hs[PREP_NPB][D];
    const int tid = threadIdx.x;
    const int i0  = blockIdx.x * PREP_NPB;

    for (int idx = tid; idx < HM * 67; idx += 512) W1s[idx] = W1[idx];
    if (tid < PREP_NPB * D) {
        int node = tid >> 5, c = tid & 31;
        hs[node][c] = g_h[cur][(i0 + node) * D + c];
    }
    if (tid < PREP_NPB * M) g_msgsum[i0 * M + tid] = 0.f;
    __syncthreads();

    const int ln = tid >> 6;        // 0..7 node
    const int k  = tid & 63;        // 0..63
    const int i  = i0 + ln;
    const float bi = b[i];
    const float* row = W1s + k * 67;
    float a  = b1[k] + bi * row[65];
    float bb = bi * row[66];
    float a1 = 0.f, b1a = 0.f;
    #pragma unroll
    for (int d0 = 0; d0 < D; d0 += 2) {
        float h0 = hs[ln][d0], h1 = hs[ln][d0 + 1];
        a   = fmaf(h0, row[d0],         a);
        a1  = fmaf(h1, row[d0 + 1],     a1);
        bb  = fmaf(h0, row[D + d0],     bb);
        b1a = fmaf(h1, row[D + d0 + 1], b1a);
    }
    g_A[i*HM + k] = a + a1;
    g_B[i*HM + k] = bb + b1a;
}

// ---------------------------------------------------------------------------
// Edge MLP (f32x2 packed): for each (i,j):
//   m1  = relu(A[i] + B[j] + J[i,j]*wJ)            (64)
//   m2  = relu(m1 @ W2^T + b2)                     (64)
//   msg = relu(m2 @ W3^T + b3)                     (32)
//   msgsum[j] += msg     (sum over i)
// ---------------------------------------------------------------------------
__global__ __launch_bounds__(256, 1)
void edge_kernel(const float* __restrict__ J,
                 const float* __restrict__ W1,
                 const float* __restrict__ W2,
                 const float* __restrict__ b2,
                 const float* __restrict__ W3,
                 const float* __restrict__ b3) {
    __shared__ __align__(16) float As[TI][HM];       // broadcast reads (per-warp same i)
    __shared__ __align__(16) float Bs[TJ][HM + 4];   // 272B rows, 16B-aligned, conflict-free
    __shared__ __align__(16) float W2s[HM][HM];      // broadcast reads
    __shared__ __align__(16) float W3Ts[HM][M];      // transposed, broadcast reads
    __shared__ __align__(16) float wJs[HM];
    __shared__ __align__(16) float b2s[HM];
    __shared__ __align__(16) float b3s[M];

    const int tid = threadIdx.x;
    const int j0 = blockIdx.x * TJ;
    const int i0 = blockIdx.y * TI;

    for (int idx = tid; idx < HM*HM; idx += 256) ((float*)W2s)[idx] = W2[idx];
    for (int idx = tid; idx < M*HM;  idx += 256) {
        int km = idx >> 6, k2 = idx & 63;   // W3 is (M, HM) row-major
        W3Ts[k2][km] = W3[idx];
    }
    for (int idx = tid; idx < TI*HM; idx += 256) ((float*)As)[idx] = g_A[i0*HM + idx];
    for (int idx = tid; idx < TJ*HM; idx += 256) {
        int r = idx >> 6, c = idx & 63;
        Bs[r][c] = g_B[j0*HM + idx];
    }
    if (tid < HM) { wJs[tid] = W1[tid*67 + 64]; b2s[tid] = b2[tid]; }
    if (tid < M)  b3s[tid] = b3[tid];

    const int g  = tid >> 5;   // i-group (warp)
    const int jj = tid & 31;   // lane -> j
    const int j  = j0 + jj;

    // Prefetch J values (batched LDGs; latency hidden under smem fill + barrier)
    float Jw_pre[LI];
    #pragma unroll
    for (int il = 0; il < LI; il++)
        Jw_pre[il] = __ldg(&J[(i0 + g*LI + il)*NN + j]);

    __syncthreads();

    u64 msgaccp[M/2];
    #pragma unroll
    for (int p = 0; p < M/2; p++) msgaccp[p] = 0ull;

    for (int il = 0; il < LI; il++) {
        const int i_local = g * LI + il;
        const u64 Jw2 = pack2(Jw_pre[il], Jw_pre[il]);

        // m1 = relu(A + B + Jw*wJ), packed pairs
        u64 m1p[HM/2];
        const ulonglong2* Ap = (const ulonglong2*)As[i_local];
        const ulonglong2* Bp = (const ulonglong2*)Bs[jj];
        const ulonglong2* Wp = (const ulonglong2*)wJs;
        #pragma unroll
        for (int k4 = 0; k4 < HM/4; k4++) {
            ulonglong2 a = Ap[k4], bb = Bp[k4], w = Wp[k4];
            m1p[2*k4+0] = relu2(fma2(Jw2, w.x, add2(a.x, bb.x)));
            m1p[2*k4+1] = relu2(fma2(Jw2, w.y, add2(a.y, bb.y)));
        }

        u64 mpp[M/2];
        #pragma unroll
        for (int p = 0; p < M/2; p++) mpp[p] = 0ull;

        // fused GEMM1 (m1 @ W2^T) + GEMM2 (relu(m2) @ W3^T), all packed f32x2
        #pragma unroll 8
        for (int k2 = 0; k2 < HM; k2++) {
            u64 c0 = 0ull, c1 = 0ull, c2 = 0ull, c3 = 0ull;  // 4 chains x 2 lanes
            const ulonglong2* w2p = (const ulonglong2*)W2s[k2];
            #pragma unroll
            for (int k4 = 0; k4 < HM/4; k4 += 2) {
                ulonglong2 wA = w2p[k4];
                ulonglong2 wB = w2p[k4+1];
                c0 = fma2(m1p[2*k4+0], wA.x, c0);
                c1 = fma2(m1p[2*k4+1], wA.y, c1);
                c2 = fma2(m1p[2*k4+2], wB.x, c2);
                c3 = fma2(m1p[2*k4+3], wB.y, c3);
            }
            u64 s = add2(add2(c0, c1), add2(c2, c3));
            float slo, shi; unpack2(s, slo, shi);
            float m2r = fmaxf(slo + shi + b2s[k2], 0.f);
            const u64 m2r2 = pack2(m2r, m2r);
            const ulonglong2* w3p = (const ulonglong2*)W3Ts[k2];
            #pragma unroll
            for (int q = 0; q < M/4; q++) {
                ulonglong2 w = w3p[q];
                mpp[2*q+0] = fma2(m2r2, w.x, mpp[2*q+0]);
                mpp[2*q+1] = fma2(m2r2, w.y, mpp[2*q+1]);
            }
        }
        // msg = relu(mp + b3); accumulate over i (packed)
        const u64* b3p = (const u64*)b3s;
        #pragma unroll
        for (int p = 0; p < M/2; p++)
            msgaccp[p] = add2(msgaccp[p], relu2(add2(mpp[p], b3p[p])));
    }

    #pragma unroll
    for (int p = 0; p < M/2; p++) {
        float lo, hi; unpack2(msgaccp[p], lo, hi);
        atomicAdd(&g_msgsum[j*M + 2*p],     lo);
        atomicAdd(&g_msgsum[j*M + 2*p + 1], hi);
    }
}

// ---------------------------------------------------------------------------
// GRU update: 4 nodes per block, 384 threads; weights staged in smem once.
// ---------------------------------------------------------------------------
#define GRU_NPB 4
__global__ __launch_bounds__(384)
void gru_kernel(const float* __restrict__ Wih,
                const float* __restrict__ Whh,
                const float* __restrict__ bih,
                const float* __restrict__ bhh,
                int cur, int nxt) {
    __shared__ float Wihs[3*D][D + M];   // 96 x 64
    __shared__ float Whhs[3*D][D];       // 96 x 32
    __shared__ float bihs[3*D], bhhs[3*D];
    __shared__ float xs[GRU_NPB][D + M];
    __shared__ float gis[GRU_NPB][3*D], ghs[GRU_NPB][3*D];

    const int tid = threadIdx.x;
    const int n0  = blockIdx.x * GRU_NPB;

    for (int idx = tid; idx < 3*D*(D+M); idx += 384) ((float*)Wihs)[idx] = Wih[idx];
    for (int idx = tid; idx < 3*D*D;     idx += 384) ((float*)Whhs)[idx] = Whh[idx];
    if (tid < 3*D) { bihs[tid] = bih[tid]; bhhs[tid] = bhh[tid]; }
    if (tid < GRU_NPB * (D + M)) {
        int node = tid >> 6, c = tid & 63;
        xs[node][c] = (c < D) ? g_h[cur][(n0 + node)*D + c]
                              : g_msgsum[(n0 + node)*M + (c - D)];
    }
    __syncthreads();

    const int ln = tid / (3*D);   // 0..3 node
    const int r  = tid % (3*D);   // 0..95 gate row

    float a0 = 0.f, a1 = 0.f, a2 = 0.f, a3 = 0.f;
    #pragma unroll
    for (int c = 0; c < D + M; c += 4) {
        a0 = fmaf(Wihs[r][c],   xs[ln][c],   a0);
        a1 = fmaf(Wihs[r][c+1], xs[ln][c+1], a1);
        a2 = fmaf(Wihs[r][c+2], xs[ln][c+2], a2);
        a3 = fmaf(Wihs[r][c+3], xs[ln][c+3], a3);
    }
    gis[ln][r] = (a0 + a1) + (a2 + a3) + bihs[r];

    float h0 = 0.f, h1 = 0.f, h2 = 0.f, h3 = 0.f;
    #pragma unroll
    for (int c = 0; c < D; c += 4) {
        h0 = fmaf(Whhs[r][c],   xs[ln][c],   h0);
        h1 = fmaf(Whhs[r][c+1], xs[ln][c+1], h1);
        h2 = fmaf(Whhs[r][c+2], xs[ln][c+2], h2);
        h3 = fmaf(Whhs[r][c+3], xs[ln][c+3], h3);
    }
    ghs[ln][r] = (h0 + h1) + (h2 + h3) + bhhs[r];
    __syncthreads();

    if (tid < GRU_NPB * D) {
        int node = tid >> 5, t = tid & 31;
        float rr = sigmoidf(gis[node][t]       + ghs[node][t]);
        float zz = sigmoidf(gis[node][D + t]   + ghs[node][D + t]);
        float ng = tanhf   (gis[node][2*D + t] + rr * ghs[node][2*D + t]);
        g_h[nxt][(n0 + node)*D + t] = (1.f - zz) * ng + zz * xs[node][t];
    }
}

// ---------------------------------------------------------------------------
// Readout: y = sigmoid(relu(relu(relu(h@W1^T+b1)@W2^T+b2)@W3^T+b3))
// ---------------------------------------------------------------------------
__global__ void readout_kernel(const float* __restrict__ rW1, const float* __restrict__ rb1,
                               const float* __restrict__ rW2, const float* __restrict__ rb2,
                               const float* __restrict__ rW3, const float* __restrict__ rb3,
                               int cur, float* __restrict__ out) {
    __shared__ float hs[D];
    __shared__ float y1[HRO], y2[HRO];
    const int n = blockIdx.x;
    const int t = threadIdx.x;   // 0..63
    if (t < D) hs[t] = g_h[cur][n*D + t];
    __syncthreads();

    float a = rb1[t];
    #pragma unroll
    for (int c = 0; c < D; c++) a = fmaf(rW1[t*D + c], hs[c], a);
    y1[t] = fmaxf(a, 0.f);
    __syncthreads();

    a = rb2[t];
    #pragma unroll
    for (int c = 0; c < HRO; c++) a = fmaf(rW2[t*HRO + c], y1[c], a);
    y2[t] = fmaxf(a, 0.f);
    __syncthreads();

    if (t < 2) {
        a = rb3[t];
        #pragma unroll
        for (int c = 0; c < HRO; c++) a = fmaf(rW3[t*HRO + c], y2[c], a);
        a = fmaxf(a, 0.f);
        out[n*2 + t] = 1.f / (1.f + expf(-a));
    }
}

// ---------------------------------------------------------------------------
extern "C" void kernel_launch(void* const* d_in, const int* in_sizes, int n_in,
                              void* d_out, int out_size) {
    const float* J   = (const float*)d_in[0];
    const float* b   = (const float*)d_in[1];
    const float* W1  = (const float*)d_in[2];
    const float* b1  = (const float*)d_in[3];
    const float* W2  = (const float*)d_in[4];
    const float* b2  = (const float*)d_in[5];
    const float* W3  = (const float*)d_in[6];
    const float* b3  = (const float*)d_in[7];
    const float* Wih = (const float*)d_in[8];
    const float* Whh = (const float*)d_in[9];
    const float* bih = (const float*)d_in[10];
    const float* bhh = (const float*)d_in[11];
    const float* rW1 = (const float*)d_in[12];
    const float* rb1 = (const float*)d_in[13];
    const float* rW2 = (const float*)d_in[14];
    const float* rb2 = (const float*)d_in[15];
    const float* rW3 = (const float*)d_in[16];
    const float* rb3 = (const float*)d_in[17];
    float* out = (float*)d_out;

    zero_h0_kernel<<<(NN*D + 255)/256, 256>>>();

    int cur = 0;
    for (int s = 0; s < NSTEPS; s++) {
        prep_kernel<<<NN/PREP_NPB, 512>>>(b, W1, b1, cur);
        edge_kernel<<<dim3(NN/TJ, NN/TI), 256>>>(J, W1, W2, b2, W3, b3);
        gru_kernel<<<NN/GRU_NPB, 384>>>(Wih, Whh, bih, bhh, cur, 1 - cur);
        cur = 1 - cur;
    }
    readout_kernel<<<NN, HRO>>>(rW1, rb1, rW2, rb2, rW3, rb3, cur, out);
}

// round 9
// speedup vs baseline: 1.1757x; 1.0037x over previous
#include <cuda_runtime.h>
#include <math.h>

#define NN      512
#define D       32
#define M       32
#define HM      64
#define HRO     64
#define NSTEPS  5

#define TJ 32      // j per block
#define LI 4       // i per thread (sequential)
#define GI 8       // i-groups (warps) per block
#define TI (LI*GI) // 32 i per block

// Scratch (device globals: no allocation allowed)
__device__ float g_h[2][NN*D];
__device__ float g_A[NN*HM];
__device__ float g_B[NN*HM];
__device__ float g_msgsum[NN*M];

typedef unsigned long long u64;

__device__ __forceinline__ float sigmoidf(float x) { return 1.f / (1.f + expf(-x)); }

// ---- packed f32x2 helpers (FFMA2: only reachable via PTX fma.rn.f32x2) ----
__device__ __forceinline__ u64 fma2(u64 a, u64 b, u64 c) {
    u64 d; asm("fma.rn.f32x2 %0, %1, %2, %3;" : "=l"(d) : "l"(a), "l"(b), "l"(c)); return d;
}
__device__ __forceinline__ u64 add2(u64 a, u64 b) {
    u64 d; asm("add.rn.f32x2 %0, %1, %2;" : "=l"(d) : "l"(a), "l"(b)); return d;
}
__device__ __forceinline__ u64 pack2(float lo, float hi) {
    u64 d; asm("mov.b64 %0, {%1, %2};" : "=l"(d) : "f"(lo), "f"(hi)); return d;
}
__device__ __forceinline__ void unpack2(u64 v, float& lo, float& hi) {
    asm("mov.b64 {%0, %1}, %2;" : "=f"(lo), "=f"(hi) : "l"(v));
}
__device__ __forceinline__ u64 relu2(u64 v) {   // FMNMX rides the alu pipe, not fma
    float lo, hi; unpack2(v, lo, hi);
    return pack2(fmaxf(lo, 0.f), fmaxf(hi, 0.f));
}

// ---------------------------------------------------------------------------
// Zero the initial hidden state (must run every replay: graph-deterministic)
// ---------------------------------------------------------------------------
__global__ void zero_h0_kernel() {
    int idx = blockIdx.x * blockDim.x + threadIdx.x;
    if (idx < NN * D) g_h[0][idx] = 0.f;
}

// ---------------------------------------------------------------------------
// Prep: A[i,k] = h[i]·Wi[k] + b[i]*wbi[k] + b1[k] ;  B[i,k] = h[i]·Wj[k] + b[i]*wbj[k]
// 8 nodes per block, 512 threads; W1 staged in smem once per block.
// Also zeroes msgsum. mp_W1 is (64, 67): [Wi(32) | Wj(32) | wJ | wbi | wbj]
// ---------------------------------------------------------------------------
#define PREP_NPB 8
__global__ __launch_bounds__(512)
void prep_kernel(const float* __restrict__ b,
                 const float* __restrict__ W1,
                 const float* __restrict__ b1,
                 int cur) {
    __shared__ float W1s[HM * 67];          // 4288 floats
    __shared__ float hs[PREP_NPB][D];
    const int tid = threadIdx.x;
    const int i0  = blockIdx.x * PREP_NPB;

    for (int idx = tid; idx < HM * 67; idx += 512) W1s[idx] = W1[idx];
    if (tid < PREP_NPB * D) {
        int node = tid >> 5, c = tid & 31;
        hs[node][c] = g_h[cur][(i0 + node) * D + c];
    }
    if (tid < PREP_NPB * M) g_msgsum[i0 * M + tid] = 0.f;
    __syncthreads();

    const int ln = tid >> 6;        // 0..7 node
    const int k  = tid & 63;        // 0..63
    const int i  = i0 + ln;
    const float bi = b[i];
    const float* row = W1s + k * 67;
    float a  = b1[k] + bi * row[65];
    float bb = bi * row[66];
    float a1 = 0.f, b1a = 0.f;
    #pragma unroll
    for (int d0 = 0; d0 < D; d0 += 2) {
        float h0 = hs[ln][d0], h1 = hs[ln][d0 + 1];
        a   = fmaf(h0, row[d0],         a);
        a1  = fmaf(h1, row[d0 + 1],     a1);
        bb  = fmaf(h0, row[D + d0],     bb);
        b1a = fmaf(h1, row[D + d0 + 1], b1a);
    }
    g_A[i*HM + k] = a + a1;
    g_B[i*HM + k] = bb + b1a;
}

// ---------------------------------------------------------------------------
// Edge MLP (f32x2 packed): for each (i,j):
//   m1  = relu(A[i] + B[j] + J[i,j]*wJ)            (64)
//   m2  = relu(m1 @ W2^T + b2)                     (64)
//   msg = relu(m2 @ W3^T + b3)                     (32)
//   msgsum[j] += msg     (sum over i)
// ---------------------------------------------------------------------------
__global__ __launch_bounds__(256, 1)
void edge_kernel(const float* __restrict__ J,
                 const float* __restrict__ W1,
                 const float* __restrict__ W2,
                 const float* __restrict__ b2,
                 const float* __restrict__ W3,
                 const float* __restrict__ b3) {
    __shared__ __align__(16) float As[TI][HM];       // broadcast reads (per-warp same i)
    __shared__ __align__(16) float Bs[TJ][HM + 4];   // 272B rows, 16B-aligned, conflict-free
    __shared__ __align__(16) float W2s[HM][HM];      // broadcast reads
    __shared__ __align__(16) float W3Ts[HM][M];      // transposed, broadcast reads
    __shared__ __align__(16) float wJs[HM];
    __shared__ __align__(16) float b2s[HM];
    __shared__ __align__(16) float b3s[M];

    const int tid = threadIdx.x;
    const int j0 = blockIdx.x * TJ;
    const int i0 = blockIdx.y * TI;

    for (int idx = tid; idx < HM*HM; idx += 256) ((float*)W2s)[idx] = W2[idx];
    for (int idx = tid; idx < M*HM;  idx += 256) {
        int km = idx >> 6, k2 = idx & 63;   // W3 is (M, HM) row-major
        W3Ts[k2][km] = W3[idx];
    }
    for (int idx = tid; idx < TI*HM; idx += 256) ((float*)As)[idx] = g_A[i0*HM + idx];
    for (int idx = tid; idx < TJ*HM; idx += 256) {
        int r = idx >> 6, c = idx & 63;
        Bs[r][c] = g_B[j0*HM + idx];
    }
    if (tid < HM) { wJs[tid] = W1[tid*67 + 64]; b2s[tid] = b2[tid]; }
    if (tid < M)  b3s[tid] = b3[tid];

    const int g  = tid >> 5;   // i-group (warp)
    const int jj = tid & 31;   // lane -> j
    const int j  = j0 + jj;

    // Prefetch J values (batched LDGs; latency hidden under smem fill + barrier)
    float Jw_pre[LI];
    #pragma unroll
    for (int il = 0; il < LI; il++)
        Jw_pre[il] = __ldg(&J[(i0 + g*LI + il)*NN + j]);

    __syncthreads();

    u64 msgaccp[M/2];
    #pragma unroll
    for (int p = 0; p < M/2; p++) msgaccp[p] = 0ull;

    for (int il = 0; il < LI; il++) {
        const int i_local = g * LI + il;
        const u64 Jw2 = pack2(Jw_pre[il], Jw_pre[il]);

        // m1 = relu(A + B + Jw*wJ), packed pairs
        u64 m1p[HM/2];
        const ulonglong2* Ap = (const ulonglong2*)As[i_local];
        const ulonglong2* Bp = (const ulonglong2*)Bs[jj];
        const ulonglong2* Wp = (const ulonglong2*)wJs;
        #pragma unroll
        for (int k4 = 0; k4 < HM/4; k4++) {
            ulonglong2 a = Ap[k4], bb = Bp[k4], w = Wp[k4];
            m1p[2*k4+0] = relu2(fma2(Jw2, w.x, add2(a.x, bb.x)));
            m1p[2*k4+1] = relu2(fma2(Jw2, w.y, add2(a.y, bb.y)));
        }

        u64 mpp[M/2];
        #pragma unroll
        for (int p = 0; p < M/2; p++) mpp[p] = 0ull;

        // fused GEMM1 (m1 @ W2^T) + GEMM2 (relu(m2) @ W3^T), all packed f32x2
        #pragma unroll 8
        for (int k2 = 0; k2 < HM; k2++) {
            u64 c0 = 0ull, c1 = 0ull, c2 = 0ull, c3 = 0ull;  // 4 chains x 2 lanes
            const ulonglong2* w2p = (const ulonglong2*)W2s[k2];
            #pragma unroll
            for (int k4 = 0; k4 < HM/4; k4 += 2) {
                ulonglong2 wA = w2p[k4];
                ulonglong2 wB = w2p[k4+1];
                c0 = fma2(m1p[2*k4+0], wA.x, c0);
                c1 = fma2(m1p[2*k4+1], wA.y, c1);
                c2 = fma2(m1p[2*k4+2], wB.x, c2);
                c3 = fma2(m1p[2*k4+3], wB.y, c3);
            }
            u64 s = add2(add2(c0, c1), add2(c2, c3));
            float slo, shi; unpack2(s, slo, shi);
            float m2r = fmaxf(slo + shi + b2s[k2], 0.f);
            const u64 m2r2 = pack2(m2r, m2r);
            const ulonglong2* w3p = (const ulonglong2*)W3Ts[k2];
            #pragma unroll
            for (int q = 0; q < M/4; q++) {
                ulonglong2 w = w3p[q];
                mpp[2*q+0] = fma2(m2r2, w.x, mpp[2*q+0]);
                mpp[2*q+1] = fma2(m2r2, w.y, mpp[2*q+1]);
            }
        }
        // msg = relu(mp + b3); accumulate over i (packed)
        const u64* b3p = (const u64*)b3s;
        #pragma unroll
        for (int p = 0; p < M/2; p++)
            msgaccp[p] = add2(msgaccp[p], relu2(add2(mpp[p], b3p[p])));
    }

    #pragma unroll
    for (int p = 0; p < M/2; p++) {
        float lo, hi; unpack2(msgaccp[p], lo, hi);
        atomicAdd(&g_msgsum[j*M + 2*p],     lo);
        atomicAdd(&g_msgsum[j*M + 2*p + 1], hi);
    }
}

// ---------------------------------------------------------------------------
// GRU update: 4 nodes per block, 384 threads; weights staged in smem once.
// ---------------------------------------------------------------------------
#define GRU_NPB 4
__global__ __launch_bounds__(384)
void gru_kernel(const float* __restrict__ Wih,
                const float* __restrict__ Whh,
                const float* __restrict__ bih,
                const float* __restrict__ bhh,
                int cur, int nxt) {
    __shared__ float Wihs[3*D][D + M];   // 96 x 64
    __shared__ float Whhs[3*D][D];       // 96 x 32
    __shared__ float bihs[3*D], bhhs[3*D];
    __shared__ float xs[GRU_NPB][D + M];
    __shared__ float gis[GRU_NPB][3*D], ghs[GRU_NPB][3*D];

    const int tid = threadIdx.x;
    const int n0  = blockIdx.x * GRU_NPB;

    for (int idx = tid; idx < 3*D*(D+M); idx += 384) ((float*)Wihs)[idx] = Wih[idx];
    for (int idx = tid; idx < 3*D*D;     idx += 384) ((float*)Whhs)[idx] = Whh[idx];
    if (tid < 3*D) { bihs[tid] = bih[tid]; bhhs[tid] = bhh[tid]; }
    if (tid < GRU_NPB * (D + M)) {
        int node = tid >> 6, c = tid & 63;
        xs[node][c] = (c < D) ? g_h[cur][(n0 + node)*D + c]
                              : g_msgsum[(n0 + node)*M + (c - D)];
    }
    __syncthreads();

    const int ln = tid / (3*D);   // 0..3 node
    const int r  = tid % (3*D);   // 0..95 gate row

    float a0 = 0.f, a1 = 0.f, a2 = 0.f, a3 = 0.f;
    #pragma unroll
    for (int c = 0; c < D + M; c += 4) {
        a0 = fmaf(Wihs[r][c],   xs[ln][c],   a0);
        a1 = fmaf(Wihs[r][c+1], xs[ln][c+1], a1);
        a2 = fmaf(Wihs[r][c+2], xs[ln][c+2], a2);
        a3 = fmaf(Wihs[r][c+3], xs[ln][c+3], a3);
    }
    gis[ln][r] = (a0 + a1) + (a2 + a3) + bihs[r];

    float h0 = 0.f, h1 = 0.f, h2 = 0.f, h3 = 0.f;
    #pragma unroll
    for (int c = 0; c < D; c += 4) {
        h0 = fmaf(Whhs[r][c],   xs[ln][c],   h0);
        h1 = fmaf(Whhs[r][c+1], xs[ln][c+1], h1);
        h2 = fmaf(Whhs[r][c+2], xs[ln][c+2], h2);
        h3 = fmaf(Whhs[r][c+3], xs[ln][c+3], h3);
    }
    ghs[ln][r] = (h0 + h1) + (h2 + h3) + bhhs[r];
    __syncthreads();

    if (tid < GRU_NPB * D) {
        int node = tid >> 5, t = tid & 31;
        float rr = sigmoidf(gis[node][t]       + ghs[node][t]);
        float zz = sigmoidf(gis[node][D + t]   + ghs[node][D + t]);
        float ng = tanhf   (gis[node][2*D + t] + rr * ghs[node][2*D + t]);
        g_h[nxt][(n0 + node)*D + t] = (1.f - zz) * ng + zz * xs[node][t];
    }
}

// ---------------------------------------------------------------------------
// Readout: y = sigmoid(relu(relu(relu(h@W1^T+b1)@W2^T+b2)@W3^T+b3))
// ---------------------------------------------------------------------------
__global__ void readout_kernel(const float* __restrict__ rW1, const float* __restrict__ rb1,
                               const float* __restrict__ rW2, const float* __restrict__ rb2,
                               const float* __restrict__ rW3, const float* __restrict__ rb3,
                               int cur, float* __restrict__ out) {
    __shared__ float hs[D];
    __shared__ float y1[HRO], y2[HRO];
    const int n = blockIdx.x;
    const int t = threadIdx.x;   // 0..63
    if (t < D) hs[t] = g_h[cur][n*D + t];
    __syncthreads();

    float a = rb1[t];
    #pragma unroll
    for (int c = 0; c < D; c++) a = fmaf(rW1[t*D + c], hs[c], a);
    y1[t] = fmaxf(a, 0.f);
    __syncthreads();

    a = rb2[t];
    #pragma unroll
    for (int c = 0; c < HRO; c++) a = fmaf(rW2[t*HRO + c], y1[c], a);
    y2[t] = fmaxf(a, 0.f);
    __syncthreads();

    if (t < 2) {
        a = rb3[t];
        #pragma unroll
        for (int c = 0; c < HRO; c++) a = fmaf(rW3[t*HRO + c], y2[c], a);
        a = fmaxf(a, 0.f);
        out[n*2 + t] = 1.f / (1.f + expf(-a));
    }
}

// ---------------------------------------------------------------------------
extern "C" void kernel_launch(void* const* d_in, const int* in_sizes, int n_in,
                              void* d_out, int out_size) {
    const float* J   = (const float*)d_in[0];
    const float* b   = (const float*)d_in[1];
    const float* W1  = (const float*)d_in[2];
    const float* b1  = (const float*)d_in[3];
    const float* W2  = (const float*)d_in[4];
    const float* b2  = (const float*)d_in[5];
    const float* W3  = (const float*)d_in[6];
    const float* b3  = (const float*)d_in[7];
    const float* Wih = (const float*)d_in[8];
    const float* Whh = (const float*)d_in[9];
    const float* bih = (const float*)d_in[10];
    const float* bhh = (const float*)d_in[11];
    const float* rW1 = (const float*)d_in[12];
    const float* rb1 = (const float*)d_in[13];
    const float* rW2 = (const float*)d_in[14];
    const float* rb2 = (const float*)d_in[15];
    const float* rW3 = (const float*)d_in[16];
    const float* rb3 = (const float*)d_in[17];
    float* out = (float*)d_out;

    zero_h0_kernel<<<(NN*D + 255)/256, 256>>>();

    int cur = 0;
    for (int s = 0; s < NSTEPS; s++) {
        prep_kernel<<<NN/PREP_NPB, 512>>>(b, W1, b1, cur);
        edge_kernel<<<dim3(NN/TJ, NN/TI), 256>>>(J, W1, W2, b2, W3, b3);
        gru_kernel<<<NN/GRU_NPB, 384>>>(Wih, Whh, bih, bhh, cur, 1 - cur);
        cur = 1 - cur;
    }
    readout_kernel<<<NN, HRO>>>(rW1, rb1, rW2, rb2, rW3, rb3, cur, out);
}

// round 11
// speedup vs baseline: 3.5161x; 2.9906x over previous
#include <cuda_runtime.h>
#include <cuda_bf16.h>
#include <math.h>
#include <cstdint>

#define NN 512
#define D  32
#define M  32
#define HM 64
#define NSTEPS 5

typedef unsigned int u32;

// ---- scratch (device globals; no allocation allowed) ----
__device__ float g_h[2][NN*D];
__device__ float g_A[NN*HM];
__device__ float g_B[NN*HM];
__device__ float g_msgsum[NN*M];
// packed bf16x2 weight planes: W2p[k/2][n] = {lo: W2[n][k], hi: W2[n][k+1]}
__device__ u32 g_W2phi[32*64], g_W2plo[32*64];
__device__ u32 g_W3phi[32*32], g_W3plo[32*32];

__device__ __forceinline__ float sigmoidf(float x){ return 1.f/(1.f+expf(-x)); }

// pack two f32 -> bf16x2 (v0 in low half), and hi/lo split
__device__ __forceinline__ u32 pkbf2(float v0, float v1){
    __nv_bfloat162 h = __float22bfloat162_rn(make_float2(v0, v1));
    return *(u32*)&h;
}
__device__ __forceinline__ void split2(float v0, float v1, u32& hi, u32& lo){
    __nv_bfloat162 h = __float22bfloat162_rn(make_float2(v0, v1));
    float r0 = v0 - __low2float(h), r1 = v1 - __high2float(h);
    __nv_bfloat162 l = __float22bfloat162_rn(make_float2(r0, r1));
    hi = *(u32*)&h; lo = *(u32*)&l;
}

// warp-level bf16 MMA, f32 accum (baseline PTX, sm_80+; no 'a' feature)
__device__ __forceinline__ void mma16816(float* c, const u32* a, u32 b0, u32 b1){
    asm volatile("mma.sync.aligned.m16n8k16.row.col.f32.bf16.bf16.f32 "
        "{%0,%1,%2,%3}, {%4,%5,%6,%7}, {%8,%9}, {%0,%1,%2,%3};"
        : "+f"(c[0]),"+f"(c[1]),"+f"(c[2]),"+f"(c[3])
        : "r"(a[0]),"r"(a[1]),"r"(a[2]),"r"(a[3]), "r"(b0),"r"(b1));
}

// ---- pack weights into bf16x2 hi/lo planes (constant per replay) ----
__global__ void split_kernel(const float* __restrict__ W2, const float* __restrict__ W3){
    int t = blockIdx.x*512 + threadIdx.x;
    if (t < 32*64){                       // GEMM1: B[k][n] = W2[n][k], K=64, N=64
        int k2 = t>>6, n = t&63;
        float w0 = W2[n*HM + 2*k2], w1 = W2[n*HM + 2*k2+1];
        u32 hi, lo; split2(w0, w1, hi, lo);
        g_W2phi[t] = hi; g_W2plo[t] = lo;
    } else if (t < 32*64 + 32*32){        // GEMM2: B[k][n] = W3[n][k], K=64, N=32
        int u = t - 32*64;
        int k2 = u>>5, n = u&31;
        float w0 = W3[n*HM + 2*k2], w1 = W3[n*HM + 2*k2+1];
        u32 hi, lo; split2(w0, w1, hi, lo);
        g_W3phi[u] = hi; g_W3plo[u] = lo;
    }
}

// ---- init: h0=0, msgsum=0, A/B for step 0 (h=0 => bias-only) ----
// mp_W1 is (64,67): [Wi(32) | Wj(32) | wJ | wbi | wbj]
__global__ __launch_bounds__(512) void init_kernel(const float* __restrict__ b,
        const float* __restrict__ W1, const float* __restrict__ b1){
    int t = blockIdx.x*512 + threadIdx.x;   // 0..32767
    int i = t>>6, k = t&63;
    float bi = b[i];
    g_A[t] = b1[k] + bi*W1[k*67+65];
    g_B[t] = bi*W1[k*67+66];
    if (k < D) g_h[0][i*D+k] = 0.f;
    else       g_msgsum[i*M + (k-D)] = 0.f;
}

// ---------------------------------------------------------------------------
// Edge kernel (HMMA): block = 4 warps, warp = 1 i x 16 j edge rows.
//   m1  = relu(A[i]+B[j]+J*wJ)  (16x64, bf16 hi/lo frags built in regs)
//   C1  = m1 @ W2^T  (mma, 3-term)   -> m2 = relu(C1+b2) re-split in regs
//   C2  = m2 @ W3^T  (mma, 3-term)   -> msg = relu(C2+b3), reduce 4 i, atomics
// ---------------------------------------------------------------------------
__global__ __launch_bounds__(128) void edge_kernel(const float* __restrict__ J,
        const float* __restrict__ W1, const float* __restrict__ b2,
        const float* __restrict__ b3){
    __shared__ u32 s_w2h[32*72];          // padded stride 72: frag loads conflict-free
    __shared__ u32 s_w2l[32*72];
    __shared__ u32 s_w3h[32*40];
    __shared__ u32 s_w3l[32*40];
    __shared__ float s_A[4][HM];
    __shared__ float s_B[16][72];
    __shared__ float s_wJ[HM], s_b2[HM], s_b3[M];

    const int tid  = threadIdx.x;
    const int wid  = tid>>5, lane = tid&31;
    const int g    = lane>>2, t = lane&3;
    const int j0   = blockIdx.x*16;
    const int i    = blockIdx.y*4 + wid;

    // stage packed weights + A/B rows + vectors
    for (int idx = tid; idx < 32*64; idx += 128){
        int r = idx>>6, c = idx&63;
        s_w2h[r*72+c] = g_W2phi[idx];
        s_w2l[r*72+c] = g_W2plo[idx];
    }
    for (int idx = tid; idx < 32*32; idx += 128){
        int r = idx>>5, c = idx&31;
        s_w3h[r*40+c] = g_W3phi[idx];
        s_w3l[r*40+c] = g_W3plo[idx];
    }
    for (int idx = tid; idx < 4*HM; idx += 128) ((float*)s_A)[idx] = g_A[(blockIdx.y*4)*HM + idx];
    for (int idx = tid; idx < 16*HM; idx += 128){
        int r = idx>>6, c = idx&63;
        s_B[r][c] = g_B[(j0+r)*HM + c];
    }
    if (tid < HM){ s_wJ[tid] = W1[tid*67+64]; s_b2[tid] = b2[tid]; }
    if (tid < M)  s_b3[tid] = b3[tid];

    const float Jg  = J[i*NN + j0 + g];
    const float Jg8 = J[i*NN + j0 + g + 8];
    __syncthreads();

    // ---- m1 A-fragments (4 k-steps x 4 regs, hi/lo) ----
    u32 ahi[4][4], alo[4][4];
    #pragma unroll
    for (int kk = 0; kk < 4; kk++){
        #pragma unroll
        for (int h = 0; h < 2; h++){
            int k = kk*16 + h*8 + t*2;
            float A0 = s_A[wid][k],  A1 = s_A[wid][k+1];
            float w0 = s_wJ[k],      w1 = s_wJ[k+1];
            float t0 = A0 + Jg *w0,  t1 = A1 + Jg *w1;
            float u0 = A0 + Jg8*w0,  u1 = A1 + Jg8*w1;
            float vg0 = fmaxf(t0 + s_B[g  ][k], 0.f), vg1 = fmaxf(t1 + s_B[g  ][k+1], 0.f);
            float v80 = fmaxf(u0 + s_B[g+8][k], 0.f), v81 = fmaxf(u1 + s_B[g+8][k+1], 0.f);
            split2(vg0, vg1, ahi[kk][2*h  ], alo[kk][2*h  ]);   // row g
            split2(v80, v81, ahi[kk][2*h+1], alo[kk][2*h+1]);   // row g+8
        }
    }

    // ---- GEMM1: C1[16x64] = m1 @ W2^T (3-term bf16) ----
    float C1[8][4];
    #pragma unroll
    for (int nt = 0; nt < 8; nt++){ C1[nt][0]=C1[nt][1]=C1[nt][2]=C1[nt][3]=0.f; }
    #pragma unroll
    for (int nt = 0; nt < 8; nt++){
        #pragma unroll
        for (int kk = 0; kk < 4; kk++){
            const u32* bh = s_w2h + (kk*8+t)*72 + nt*8 + g;
            const u32* bl = s_w2l + (kk*8+t)*72 + nt*8 + g;
            u32 bh0 = bh[0], bh1 = bh[4*72];
            u32 bl0 = bl[0], bl1 = bl[4*72];
            mma16816(C1[nt], ahi[kk], bh0, bh1);
            mma16816(C1[nt], alo[kk], bh0, bh1);
            mma16816(C1[nt], ahi[kk], bl0, bl1);
        }
    }

    // ---- m2 = relu(C1 + b2): C-frag layout == A-frag layout, regs only ----
    u32 mhi[4][4], mlo[4][4];
    #pragma unroll
    for (int kk = 0; kk < 4; kk++){
        #pragma unroll
        for (int p = 0; p < 2; p++){
            int nt = 2*kk + p;
            float bb0 = s_b2[nt*8 + t*2], bb1 = s_b2[nt*8 + t*2 + 1];
            float v0 = fmaxf(C1[nt][0]+bb0, 0.f), v1 = fmaxf(C1[nt][1]+bb1, 0.f);
            float v2 = fmaxf(C1[nt][2]+bb0, 0.f), v3 = fmaxf(C1[nt][3]+bb1, 0.f);
            split2(v0, v1, mhi[kk][2*p  ], mlo[kk][2*p  ]);
            split2(v2, v3, mhi[kk][2*p+1], mlo[kk][2*p+1]);
        }
    }

    // ---- GEMM2: C2[16x32] = m2 @ W3^T (3-term bf16) ----
    float C2[4][4];
    #pragma unroll
    for (int nt = 0; nt < 4; nt++){ C2[nt][0]=C2[nt][1]=C2[nt][2]=C2[nt][3]=0.f; }
    #pragma unroll
    for (int nt = 0; nt < 4; nt++){
        #pragma unroll
        for (int kk = 0; kk < 4; kk++){
            const u32* bh = s_w3h + (kk*8+t)*40 + nt*8 + g;
            const u32* bl = s_w3l + (kk*8+t)*40 + nt*8 + g;
            u32 bh0 = bh[0], bh1 = bh[4*40];
            u32 bl0 = bl[0], bl1 = bl[4*40];
            mma16816(C2[nt], mhi[kk], bh0, bh1);
            mma16816(C2[nt], mlo[kk], bh0, bh1);
            mma16816(C2[nt], mhi[kk], bl0, bl1);
        }
    }

    // ---- msg = relu(C2+b3); reduce over 4 warps (i's); atomics per j ----
    __syncthreads();                       // all warps done reading s_w2h
    float* red = (float*)s_w2h;            // reuse: 4 warps x 16 x 33 = 8448B
    #pragma unroll
    for (int nt = 0; nt < 4; nt++){
        int c = nt*8 + t*2;
        float bb0 = s_b3[c], bb1 = s_b3[c+1];
        red[wid*528 + g*33      + c    ] = fmaxf(C2[nt][0]+bb0, 0.f);
        red[wid*528 + g*33      + c + 1] = fmaxf(C2[nt][1]+bb1, 0.f);
        red[wid*528 + (g+8)*33  + c    ] = fmaxf(C2[nt][2]+bb0, 0.f);
        red[wid*528 + (g+8)*33  + c + 1] = fmaxf(C2[nt][3]+bb1, 0.f);
    }
    __syncthreads();
    #pragma unroll
    for (int v = tid; v < 16*32; v += 128){
        int r = v>>5, c = v&31;
        float s = red[r*33+c] + red[528+r*33+c] + red[1056+r*33+c] + red[1584+r*33+c];
        atomicAdd(&g_msgsum[(j0+r)*M + c], s);
    }
}

// ---- fused GRU + next-step A/B prep: 4 nodes/block, 384 threads ----
__global__ __launch_bounds__(384) void update_kernel(
        const float* __restrict__ Wih, const float* __restrict__ Whh,
        const float* __restrict__ bih, const float* __restrict__ bhh,
        const float* __restrict__ b,   const float* __restrict__ W1,
        const float* __restrict__ b1,  int cur, int nxt){
    __shared__ float Wihs[3*D][D+M];
    __shared__ float Whhs[3*D][D];
    __shared__ float bihs[3*D], bhhs[3*D];
    __shared__ float xs[4][D+M], gis[4][3*D], ghs[4][3*D], hn[4][D];
    const int tid = threadIdx.x, n0 = blockIdx.x*4;

    #pragma unroll
    for (int idx=tid; idx<3*D*(D+M)/4; idx+=384) ((float4*)Wihs)[idx]=((const float4*)Wih)[idx];
    #pragma unroll
    for (int idx=tid; idx<3*D*D/4; idx+=384) ((float4*)Whhs)[idx]=((const float4*)Whh)[idx];
    if (tid<3*D){ bihs[tid]=bih[tid]; bhhs[tid]=bhh[tid]; }
    if (tid<4*(D+M)){ int nd=tid>>6, c=tid&63;
        xs[nd][c]=(c<D)?g_h[cur][(n0+nd)*D+c]:g_msgsum[(n0+nd)*M+(c-D)];
    }
    __syncthreads();

    const int ln=tid/(3*D), r=tid%(3*D);
    float a0=0,a1=0,a2=0,a3=0;
    #pragma unroll
    for (int c=0;c<D+M;c+=4){
        a0=fmaf(Wihs[r][c],xs[ln][c],a0);     a1=fmaf(Wihs[r][c+1],xs[ln][c+1],a1);
        a2=fmaf(Wihs[r][c+2],xs[ln][c+2],a2); a3=fmaf(Wihs[r][c+3],xs[ln][c+3],a3);
    }
    gis[ln][r]=(a0+a1)+(a2+a3)+bihs[r];
    float h0=0,h1=0,h2=0,h3=0;
    #pragma unroll
    for (int c=0;c<D;c+=4){
        h0=fmaf(Whhs[r][c],xs[ln][c],h0);     h1=fmaf(Whhs[r][c+1],xs[ln][c+1],h1);
        h2=fmaf(Whhs[r][c+2],xs[ln][c+2],h2); h3=fmaf(Whhs[r][c+3],xs[ln][c+3],h3);
    }
    ghs[ln][r]=(h0+h1)+(h2+h3)+bhhs[r];
    __syncthreads();

    if (tid<4*D){
        int nd=tid>>5, tt=tid&31;
        float rr=sigmoidf(gis[nd][tt]+ghs[nd][tt]);
        float zz=sigmoidf(gis[nd][D+tt]+ghs[nd][D+tt]);
        float ng=tanhf(gis[nd][2*D+tt]+rr*ghs[nd][2*D+tt]);
        float hv=(1.f-zz)*ng+zz*xs[nd][tt];
        hn[nd][tt]=hv;
        g_h[nxt][(n0+nd)*D+tt]=hv;
        g_msgsum[(n0+nd)*M+tt]=0.f;          // re-zero for next step
    }
    __syncthreads();

    if (tid<256){                             // next-step A/B from h_new
        int nd=tid>>6, k=tid&63, i=n0+nd;
        float bi=b[i];
        const float* row=W1+k*67;
        float a=b1[k]+bi*__ldg(row+65), bb=bi*__ldg(row+66);
        float ax=0.f, bx=0.f;
        #pragma unroll
        for (int d0=0; d0<D; d0+=2){
            float hv0=hn[nd][d0], hv1=hn[nd][d0+1];
            a =fmaf(hv0,__ldg(row+d0),a);      ax=fmaf(hv1,__ldg(row+d0+1),ax);
            bb=fmaf(hv0,__ldg(row+D+d0),bb);   bx=fmaf(hv1,__ldg(row+D+d0+1),bx);
        }
        g_A[i*HM+k]=a+ax;
        g_B[i*HM+k]=bb+bx;
    }
}

// ---- readout ----
__global__ void readout_kernel(const float* __restrict__ rW1,const float* __restrict__ rb1,
        const float* __restrict__ rW2,const float* __restrict__ rb2,
        const float* __restrict__ rW3,const float* __restrict__ rb3,
        int cur, float* __restrict__ out){
    __shared__ float hs[D], y1[HM], y2[HM];
    const int n=blockIdx.x, t=threadIdx.x;
    if (t<D) hs[t]=g_h[cur][n*D+t];
    __syncthreads();
    float a=rb1[t];
    #pragma unroll
    for (int c=0;c<D;c++) a=fmaf(rW1[t*D+c],hs[c],a);
    y1[t]=fmaxf(a,0.f);
    __syncthreads();
    a=rb2[t];
    #pragma unroll
    for (int c=0;c<HM;c++) a=fmaf(rW2[t*HM+c],y1[c],a);
    y2[t]=fmaxf(a,0.f);
    __syncthreads();
    if (t<2){
        a=rb3[t];
        #pragma unroll
        for (int c=0;c<HM;c++) a=fmaf(rW3[t*HM+c],y2[c],a);
        out[n*2+t]=1.f/(1.f+expf(-fmaxf(a,0.f)));
    }
}

extern "C" void kernel_launch(void* const* d_in, const int* in_sizes, int n_in,
                              void* d_out, int out_size){
    const float* J  =(const float*)d_in[0];
    const float* b  =(const float*)d_in[1];
    const float* W1 =(const float*)d_in[2];
    const float* b1 =(const float*)d_in[3];
    const float* W2 =(const float*)d_in[4];
    const float* b2 =(const float*)d_in[5];
    const float* W3 =(const float*)d_in[6];
    const float* b3 =(const float*)d_in[7];
    const float* Wih=(const float*)d_in[8];
    const float* Whh=(const float*)d_in[9];
    const float* bih=(const float*)d_in[10];
    const float* bhh=(const float*)d_in[11];
    const float* rW1=(const float*)d_in[12];
    const float* rb1=(const float*)d_in[13];
    const float* rW2=(const float*)d_in[14];
    const float* rb2=(const float*)d_in[15];
    const float* rW3=(const float*)d_in[16];
    const float* rb3=(const float*)d_in[17];
    float* out=(float*)d_out;

    init_kernel<<<64,512>>>(b, W1, b1);
    split_kernel<<<6,512>>>(W2, W3);

    int cur=0;
    for (int s=0;s<NSTEPS;s++){
        edge_kernel<<<dim3(NN/16, NN/4),128>>>(J, W1, b2, b3);
        update_kernel<<<NN/4,384>>>(Wih, Whh, bih, bhh, b, W1, b1, cur, 1-cur);
        cur = 1-cur;
    }
    readout_kernel<<<NN,HM>>>(rW1, rb1, rW2, rb2, rW3, rb3, cur, out);
}

// round 12
// speedup vs baseline: 5.1475x; 1.4640x over previous
#include <cuda_runtime.h>
#include <cuda_bf16.h>
#include <math.h>
#include <cstdint>

#define NN 512
#define D  32
#define M  32
#define HM 64
#define NSTEPS 5

typedef unsigned int u32;

// ---- scratch (device globals; no allocation allowed) ----
__device__ float g_h[2][NN*D];
__device__ float g_A[NN*HM];
__device__ float g_B[NN*HM];
__device__ float g_msgsum[NN*M];
// packed bf16x2 weight planes: W2p[k/2][n] = {lo half: W2[n][2k], hi half: W2[n][2k+1]}
__device__ u32 g_W2phi[32*64], g_W2plo[32*64];
__device__ u32 g_W3phi[32*32], g_W3plo[32*32];

__device__ __forceinline__ float sigmoidf(float x){ return 1.f/(1.f+expf(-x)); }

__device__ __forceinline__ void split2(float v0, float v1, u32& hi, u32& lo){
    __nv_bfloat162 h = __float22bfloat162_rn(make_float2(v0, v1));
    float r0 = v0 - __low2float(h), r1 = v1 - __high2float(h);
    __nv_bfloat162 l = __float22bfloat162_rn(make_float2(r0, r1));
    hi = *(u32*)&h; lo = *(u32*)&l;
}

// warp-level bf16 MMA, f32 accum (baseline PTX, sm_80+)
__device__ __forceinline__ void mma16816(float* c, const u32* a, u32 b0, u32 b1){
    asm volatile("mma.sync.aligned.m16n8k16.row.col.f32.bf16.bf16.f32 "
        "{%0,%1,%2,%3}, {%4,%5,%6,%7}, {%8,%9}, {%0,%1,%2,%3};"
        : "+f"(c[0]),"+f"(c[1]),"+f"(c[2]),"+f"(c[3])
        : "r"(a[0]),"r"(a[1]),"r"(a[2]),"r"(a[3]), "r"(b0),"r"(b1));
}

// ---- pack weights into bf16x2 hi/lo planes (constant per replay) ----
__global__ void split_kernel(const float* __restrict__ W2, const float* __restrict__ W3){
    int t = blockIdx.x*512 + threadIdx.x;
    if (t < 32*64){                       // B[k][n] = W2[n][k], K=64, N=64
        int k2 = t>>6, n = t&63;
        u32 hi, lo; split2(W2[n*HM + 2*k2], W2[n*HM + 2*k2+1], hi, lo);
        g_W2phi[t] = hi; g_W2plo[t] = lo;
    } else if (t < 32*64 + 32*32){        // B[k][n] = W3[n][k], K=64, N=32
        int u = t - 32*64;
        int k2 = u>>5, n = u&31;
        u32 hi, lo; split2(W3[n*HM + 2*k2], W3[n*HM + 2*k2+1], hi, lo);
        g_W3phi[u] = hi; g_W3plo[u] = lo;
    }
}

// ---- init: h0=0, msgsum=0, A/B for step 0 (h=0 => bias-only) ----
// mp_W1 is (64,67): [Wi(32) | Wj(32) | wJ | wbi | wbj]
__global__ __launch_bounds__(512) void init_kernel(const float* __restrict__ b,
        const float* __restrict__ W1, const float* __restrict__ b1){
    int t = blockIdx.x*512 + threadIdx.x;   // 0..32767
    int i = t>>6, k = t&63;
    float bi = b[i];
    g_A[t] = b1[k] + bi*W1[k*67+65];
    g_B[t] = bi*W1[k*67+66];
    if (k < D) g_h[0][i*D+k] = 0.f;
    else       g_msgsum[i*M + (k-D)] = 0.f;
}

// ---------------------------------------------------------------------------
// Edge kernel (HMMA): block = 4 warps; tile = 4 i x 32 j via TWO j-passes
// reusing the staged weights (halves L2 weight traffic + block count vs R11).
// Warp per pass: 1 i x 16 j edge rows.
//   m1 = relu(A[i]+B[j]+J*wJ) -> bf16 hi/lo frags (regs)
//   C1 = m1 @ W2^T (3-term)   -> m2 = relu(C1+b2) re-split (regs only)
//   C2 = m2 @ W3^T (3-term)   -> msg = relu(C2+b3), 4-warp smem reduce, atomics
// ---------------------------------------------------------------------------
__global__ __launch_bounds__(128) void edge_kernel(const float* __restrict__ J,
        const float* __restrict__ W1, const float* __restrict__ b2,
        const float* __restrict__ b3){
    __shared__ u32   s_wbuf[7168];        // w2h[2304] w2l[2304] w3h[1280] w3l[1280]
    __shared__ float s_A[4][HM];
    __shared__ float s_B[32][72];         // padded: frag reads conflict-free
    __shared__ float s_red[4*16*33];      // 4 warps x 16 rows x 33 (padded)
    __shared__ float s_wJ[HM], s_b2[HM], s_b3[M];

    u32* s_w2h = s_wbuf;
    u32* s_w2l = s_wbuf + 2304;
    u32* s_w3h = s_wbuf + 4608;
    u32* s_w3l = s_wbuf + 5888;

    const int tid  = threadIdx.x;
    const int wid  = tid>>5, lane = tid&31;
    const int g    = lane>>2, t = lane&3;
    const int j0   = blockIdx.x*32;
    const int i    = blockIdx.y*4 + wid;

    // ---- stage packed weights (uint4) + A/B rows (float4) + vectors ----
    {
        const uint4* s2h = (const uint4*)g_W2phi;
        const uint4* s2l = (const uint4*)g_W2plo;
        #pragma unroll
        for (int idx = tid; idx < 512; idx += 128){      // 32x64 u32 = 512 uint4
            int r = idx>>4, c4 = idx&15;
            *(uint4*)(s_w2h + r*72 + c4*4) = s2h[idx];
            *(uint4*)(s_w2l + r*72 + c4*4) = s2l[idx];
        }
        const uint4* s3h = (const uint4*)g_W3phi;
        const uint4* s3l = (const uint4*)g_W3plo;
        #pragma unroll
        for (int idx = tid; idx < 256; idx += 128){      // 32x32 u32 = 256 uint4
            int r = idx>>3, c4 = idx&7;
            *(uint4*)(s_w3h + r*40 + c4*4) = s3h[idx];
            *(uint4*)(s_w3l + r*40 + c4*4) = s3l[idx];
        }
        const float4* Bg = (const float4*)(g_B + j0*HM);
        #pragma unroll
        for (int idx = tid; idx < 512; idx += 128){      // 32 rows x 16 float4
            int r = idx>>4, c4 = idx&15;
            *(float4*)(&s_B[r][c4*4]) = Bg[idx];
        }
        const float4* Ag = (const float4*)(g_A + blockIdx.y*4*HM);
        #pragma unroll
        for (int idx = tid; idx < 64; idx += 128)
            *(float4*)(((float*)s_A) + idx*4) = Ag[idx];
        if (tid < HM){ s_wJ[tid] = W1[tid*67+64]; s_b2[tid] = b2[tid]; }
        if (tid < M)  s_b3[tid] = b3[tid];
    }

    // prefetch all 4 J values (2 per pass) before the barrier
    float Jp[2][2];
    #pragma unroll
    for (int p = 0; p < 2; p++){
        Jp[p][0] = J[i*NN + j0 + p*16 + g];
        Jp[p][1] = J[i*NN + j0 + p*16 + g + 8];
    }
    __syncthreads();

    #pragma unroll
    for (int pass = 0; pass < 2; pass++){
        const int jb = pass*16;
        const float Jg = Jp[pass][0], Jg8 = Jp[pass][1];

        // ---- m1 A-fragments (4 k-steps x 4 regs, hi/lo) ----
        u32 ahi[4][4], alo[4][4];
        #pragma unroll
        for (int kk = 0; kk < 4; kk++){
            #pragma unroll
            for (int h = 0; h < 2; h++){
                int k = kk*16 + h*8 + t*2;
                float A0 = s_A[wid][k],  A1 = s_A[wid][k+1];
                float w0 = s_wJ[k],      w1 = s_wJ[k+1];
                float t0 = A0 + Jg *w0,  t1 = A1 + Jg *w1;
                float u0 = A0 + Jg8*w0,  u1 = A1 + Jg8*w1;
                float vg0 = fmaxf(t0 + s_B[jb+g  ][k], 0.f), vg1 = fmaxf(t1 + s_B[jb+g  ][k+1], 0.f);
                float v80 = fmaxf(u0 + s_B[jb+g+8][k], 0.f), v81 = fmaxf(u1 + s_B[jb+g+8][k+1], 0.f);
                split2(vg0, vg1, ahi[kk][2*h  ], alo[kk][2*h  ]);
                split2(v80, v81, ahi[kk][2*h+1], alo[kk][2*h+1]);
            }
        }

        // ---- GEMM1: C1[16x64] = m1 @ W2^T (3-term bf16) ----
        float C1[8][4];
        #pragma unroll
        for (int nt = 0; nt < 8; nt++){ C1[nt][0]=C1[nt][1]=C1[nt][2]=C1[nt][3]=0.f; }
        #pragma unroll
        for (int nt = 0; nt < 8; nt++){
            #pragma unroll
            for (int kk = 0; kk < 4; kk++){
                const u32* bh = s_w2h + (kk*8+t)*72 + nt*8 + g;
                const u32* bl = s_w2l + (kk*8+t)*72 + nt*8 + g;
                u32 bh0 = bh[0], bh1 = bh[4*72];
                u32 bl0 = bl[0], bl1 = bl[4*72];
                mma16816(C1[nt], ahi[kk], bh0, bh1);
                mma16816(C1[nt], alo[kk], bh0, bh1);
                mma16816(C1[nt], ahi[kk], bl0, bl1);
            }
        }

        // ---- m2 = relu(C1+b2): C-frag layout == A-frag layout (regs only) ----
        u32 mhi[4][4], mlo[4][4];
        #pragma unroll
        for (int kk = 0; kk < 4; kk++){
            #pragma unroll
            for (int p = 0; p < 2; p++){
                int nt = 2*kk + p;
                float bb0 = s_b2[nt*8 + t*2], bb1 = s_b2[nt*8 + t*2 + 1];
                float v0 = fmaxf(C1[nt][0]+bb0, 0.f), v1 = fmaxf(C1[nt][1]+bb1, 0.f);
                float v2 = fmaxf(C1[nt][2]+bb0, 0.f), v3 = fmaxf(C1[nt][3]+bb1, 0.f);
                split2(v0, v1, mhi[kk][2*p  ], mlo[kk][2*p  ]);
                split2(v2, v3, mhi[kk][2*p+1], mlo[kk][2*p+1]);
            }
        }

        // ---- GEMM2: C2[16x32] = m2 @ W3^T (3-term bf16) ----
        float C2[4][4];
        #pragma unroll
        for (int nt = 0; nt < 4; nt++){ C2[nt][0]=C2[nt][1]=C2[nt][2]=C2[nt][3]=0.f; }
        #pragma unroll
        for (int nt = 0; nt < 4; nt++){
            #pragma unroll
            for (int kk = 0; kk < 4; kk++){
                const u32* bh = s_w3h + (kk*8+t)*40 + nt*8 + g;
                const u32* bl = s_w3l + (kk*8+t)*40 + nt*8 + g;
                u32 bh0 = bh[0], bh1 = bh[4*40];
                u32 bl0 = bl[0], bl1 = bl[4*40];
                mma16816(C2[nt], mhi[kk], bh0, bh1);
                mma16816(C2[nt], mlo[kk], bh0, bh1);
                mma16816(C2[nt], mhi[kk], bl0, bl1);
            }
        }

        // ---- msg = relu(C2+b3); reduce over 4 warps (i's); atomics per j ----
        #pragma unroll
        for (int nt = 0; nt < 4; nt++){
            int c = nt*8 + t*2;
            float bb0 = s_b3[c], bb1 = s_b3[c+1];
            s_red[wid*528 + g*33     + c    ] = fmaxf(C2[nt][0]+bb0, 0.f);
            s_red[wid*528 + g*33     + c + 1] = fmaxf(C2[nt][1]+bb1, 0.f);
            s_red[wid*528 + (g+8)*33 + c    ] = fmaxf(C2[nt][2]+bb0, 0.f);
            s_red[wid*528 + (g+8)*33 + c + 1] = fmaxf(C2[nt][3]+bb1, 0.f);
        }
        __syncthreads();
        #pragma unroll
        for (int v = tid; v < 512; v += 128){
            int r = v>>5, c = v&31;
            float s = s_red[r*33+c] + s_red[528+r*33+c] + s_red[1056+r*33+c] + s_red[1584+r*33+c];
            atomicAdd(&g_msgsum[(j0+jb+r)*M + c], s);
        }
        __syncthreads();   // protect s_red before next pass rewrites it
    }
}

// ---------------------------------------------------------------------------
// Fused GRU + next-step A/B prep. Padded smem (stride 65/33) kills the 32-way
// LDS bank conflicts; W1 staged into the dead Wihs region for the prep phase.
// ---------------------------------------------------------------------------
__global__ __launch_bounds__(384) void update_kernel(
        const float* __restrict__ Wih, const float* __restrict__ Whh,
        const float* __restrict__ bih, const float* __restrict__ bhh,
        const float* __restrict__ b,   const float* __restrict__ W1,
        const float* __restrict__ b1,  int cur, int nxt){
    __shared__ float Wihs[3*D][D+M+1];   // stride 65: bank = (r+c)%32, conflict-free
    __shared__ float Whhs[3*D][D+1];     // stride 33
    __shared__ float bihs[3*D], bhhs[3*D];
    __shared__ float xs[4][D+M], gis[4][3*D], ghs[4][3*D], hn[4][D];
    const int tid = threadIdx.x, n0 = blockIdx.x*4;

    for (int idx = tid; idx < 3*D*(D+M); idx += 384) Wihs[idx>>6][idx&63] = Wih[idx];
    for (int idx = tid; idx < 3*D*D;     idx += 384) Whhs[idx>>5][idx&31] = Whh[idx];
    if (tid < 3*D){ bihs[tid] = bih[tid]; bhhs[tid] = bhh[tid]; }
    if (tid < 4*(D+M)){ int nd = tid>>6, c = tid&63;
        xs[nd][c] = (c < D) ? g_h[cur][(n0+nd)*D+c] : g_msgsum[(n0+nd)*M+(c-D)];
    }
    __syncthreads();

    const int ln = tid/(3*D), r = tid%(3*D);
    float a0=0,a1=0,a2=0,a3=0;
    #pragma unroll
    for (int c = 0; c < D+M; c += 4){
        a0=fmaf(Wihs[r][c],xs[ln][c],a0);     a1=fmaf(Wihs[r][c+1],xs[ln][c+1],a1);
        a2=fmaf(Wihs[r][c+2],xs[ln][c+2],a2); a3=fmaf(Wihs[r][c+3],xs[ln][c+3],a3);
    }
    gis[ln][r]=(a0+a1)+(a2+a3)+bihs[r];
    float h0=0,h1=0,h2=0,h3=0;
    #pragma unroll
    for (int c = 0; c < D; c += 4){
        h0=fmaf(Whhs[r][c],xs[ln][c],h0);     h1=fmaf(Whhs[r][c+1],xs[ln][c+1],h1);
        h2=fmaf(Whhs[r][c+2],xs[ln][c+2],h2); h3=fmaf(Whhs[r][c+3],xs[ln][c+3],h3);
    }
    ghs[ln][r]=(h0+h1)+(h2+h3)+bhhs[r];
    __syncthreads();   // Wihs/Whhs fully consumed below this point

    // stage W1 (64x67 = 4288 floats) into the dead Wihs region, coalesced
    float* W1s = (float*)Wihs;
    for (int idx = tid; idx < HM*67; idx += 384) W1s[idx] = W1[idx];

    if (tid < 4*D){
        int nd = tid>>5, tt = tid&31;
        float rr = sigmoidf(gis[nd][tt]      + ghs[nd][tt]);
        float zz = sigmoidf(gis[nd][D+tt]    + ghs[nd][D+tt]);
        float ng = tanhf   (gis[nd][2*D+tt]  + rr*ghs[nd][2*D+tt]);
        float hv = (1.f-zz)*ng + zz*xs[nd][tt];
        hn[nd][tt] = hv;
        g_h[nxt][(n0+nd)*D+tt] = hv;
        g_msgsum[(n0+nd)*M+tt] = 0.f;        // re-zero for next step
    }
    __syncthreads();

    if (tid < 256){                           // next-step A/B from h_new
        int nd = tid>>6, k = tid&63, i = n0+nd;
        float bi = b[i];
        const float* row = W1s + k*67;        // smem; (3k+c)%32: conflict-free
        float a = b1[k] + bi*row[65], bb = bi*row[66];
        float ax = 0.f, bx = 0.f;
        #pragma unroll
        for (int d0 = 0; d0 < D; d0 += 2){
            float hv0 = hn[nd][d0], hv1 = hn[nd][d0+1];
            a  = fmaf(hv0, row[d0],     a);    ax = fmaf(hv1, row[d0+1],   ax);
            bb = fmaf(hv0, row[D+d0],  bb);    bx = fmaf(hv1, row[D+d0+1], bx);
        }
        g_A[i*HM+k] = a + ax;
        g_B[i*HM+k] = bb + bx;
    }
}

// ---- readout ----
__global__ void readout_kernel(const float* __restrict__ rW1,const float* __restrict__ rb1,
        const float* __restrict__ rW2,const float* __restrict__ rb2,
        const float* __restrict__ rW3,const float* __restrict__ rb3,
        int cur, float* __restrict__ out){
    __shared__ float hs[D], y1[HM], y2[HM];
    const int n = blockIdx.x, t = threadIdx.x;
    if (t < D) hs[t] = g_h[cur][n*D+t];
    __syncthreads();
    float a = rb1[t];
    #pragma unroll
    for (int c = 0; c < D; c++) a = fmaf(rW1[t*D+c], hs[c], a);
    y1[t] = fmaxf(a, 0.f);
    __syncthreads();
    a = rb2[t];
    #pragma unroll
    for (int c = 0; c < HM; c++) a = fmaf(rW2[t*HM+c], y1[c], a);
    y2[t] = fmaxf(a, 0.f);
    __syncthreads();
    if (t < 2){
        a = rb3[t];
        #pragma unroll
        for (int c = 0; c < HM; c++) a = fmaf(rW3[t*HM+c], y2[c], a);
        out[n*2+t] = 1.f/(1.f+expf(-fmaxf(a, 0.f)));
    }
}

extern "C" void kernel_launch(void* const* d_in, const int* in_sizes, int n_in,
                              void* d_out, int out_size){
    const float* J  =(const float*)d_in[0];
    const float* b  =(const float*)d_in[1];
    const float* W1 =(const float*)d_in[2];
    const float* b1 =(const float*)d_in[3];
    const float* W2 =(const float*)d_in[4];
    const float* b2 =(const float*)d_in[5];
    const float* W3 =(const float*)d_in[6];
    const float* b3 =(const float*)d_in[7];
    const float* Wih=(const float*)d_in[8];
    const float* Whh=(const float*)d_in[9];
    const float* bih=(const float*)d_in[10];
    const float* bhh=(const float*)d_in[11];
    const float* rW1=(const float*)d_in[12];
    const float* rb1=(const float*)d_in[13];
    const float* rW2=(const float*)d_in[14];
    const float* rb2=(const float*)d_in[15];
    const float* rW3=(const float*)d_in[16];
    const float* rb3=(const float*)d_in[17];
    float* out = (float*)d_out;

    init_kernel<<<64,512>>>(b, W1, b1);
    split_kernel<<<6,512>>>(W2, W3);

    int cur = 0;
    for (int s = 0; s < NSTEPS; s++){
        edge_kernel<<<dim3(NN/32, NN/4),128>>>(J, W1, b2, b3);
        update_kernel<<<NN/4,384>>>(Wih, Whh, bih, bhh, b, W1, b1, cur, 1-cur);
        cur = 1-cur;
    }
    readout_kernel<<<NN,HM>>>(rW1, rb1, rW2, rb2, rW3, rb3, cur, out);
}